// round 2
// baseline (speedup 1.0000x reference)
#include <cuda_runtime.h>
#include <math_constants.h>

// HierarchicalSoftmax: x [B, 520] fp32. Per row: softmax over cols [0,8)
// (heads) and over each 64-col children group g: [8+64g, 8+64(g+1)).
// All boundaries are float4-aligned; a pair of adjacent children groups is
// 32 contiguous float4s (512B) -> one warp-wide LDG.128 is fully coalesced
// and each 16-lane half-warp owns exactly one segment (butterfly offsets
// 8,4,2,1 stay inside the half-warp).
//
// R2: TWO rows per warp. 8 pair-loads + 1 dual-sector head load issued up
// front (MLP~9) to keep the LSU queue full; both rows' head softmaxes share
// one shuffle sequence (lanes 0-7 = row0 heads, lanes 16-23 = row1 heads).
// Streaming cache hints (.cs) since every byte is touched exactly once.

#define NCOLS 520

__global__ __launch_bounds__(256) void hsoftmax_kernel(
    const float* __restrict__ x,
    float* __restrict__ out,
    int nrows)
{
    const unsigned FULL = 0xffffffffu;
    int warp = (blockIdx.x * blockDim.x + threadIdx.x) >> 5;
    int lane = threadIdx.x & 31;
    int r0 = warp * 2;
    if (r0 >= nrows) return;

    const float* xr0 = x + (size_t)r0 * NCOLS;
    const float* xr1 = xr0 + NCOLS;          // nrows is even (65536)
    float* or0 = out + (size_t)r0 * NCOLS;
    float* or1 = or0 + NCOLS;
    const float4* x40 = reinterpret_cast<const float4*>(xr0);
    const float4* x41 = reinterpret_cast<const float4*>(xr1);
    float4* o40 = reinterpret_cast<float4*>(or0);
    float4* o41 = reinterpret_cast<float4*>(or1);

    // ---- Issue all loads up front ----
    // Heads for BOTH rows in one LDG: lanes 0-7 -> row0 cols 0-7,
    // lanes 16-23 -> row1 cols 0-7 (two 32B sectors).
    int hl = lane & 15;
    const float* hb = (lane < 16) ? xr0 : xr1;
    float hv = (hl < 8) ? __ldcs(hb + hl) : -CUDART_INF_F;

    // Children pair-loads: 4 per row, each a warp-wide contiguous 512B LDG.128.
    float4 a0 = __ldcs(&x40[2 + 32 * 0 + lane]);
    float4 a1 = __ldcs(&x40[2 + 32 * 1 + lane]);
    float4 a2 = __ldcs(&x40[2 + 32 * 2 + lane]);
    float4 a3 = __ldcs(&x40[2 + 32 * 3 + lane]);
    float4 b0 = __ldcs(&x41[2 + 32 * 0 + lane]);
    float4 b1 = __ldcs(&x41[2 + 32 * 1 + lane]);
    float4 b2 = __ldcs(&x41[2 + 32 * 2 + lane]);
    float4 b3 = __ldcs(&x41[2 + 32 * 3 + lane]);

    // ---- Heads softmax, both rows at once ----
    // Offsets 4,2,1 keep the butterfly inside each 8-lane group; lanes 8-15
    // and 24-31 carry -inf junk (their exp is NaN but never stored/summed
    // into the live groups).
    {
        float m = hv;
        m = fmaxf(m, __shfl_xor_sync(FULL, m, 4));
        m = fmaxf(m, __shfl_xor_sync(FULL, m, 2));
        m = fmaxf(m, __shfl_xor_sync(FULL, m, 1));
        float e = __expf(hv - m);
        float s = e;
        s += __shfl_xor_sync(FULL, s, 4);
        s += __shfl_xor_sync(FULL, s, 2);
        s += __shfl_xor_sync(FULL, s, 1);
        if (hl < 8) {
            float* ob = (lane < 16) ? or0 : or1;
            __stcs(ob + hl, e / s);
        }
    }

    // ---- Children: each 16-lane half owns one 64-elem group ----
    float4 va[4] = {a0, a1, a2, a3};
    float4 vb[4] = {b0, b1, b2, b3};
#pragma unroll
    for (int j = 0; j < 4; ++j) {
#pragma unroll
        for (int r = 0; r < 2; ++r) {
            float4 v = r ? vb[j] : va[j];
            float m = fmaxf(fmaxf(v.x, v.y), fmaxf(v.z, v.w));
            m = fmaxf(m, __shfl_xor_sync(FULL, m, 8));
            m = fmaxf(m, __shfl_xor_sync(FULL, m, 4));
            m = fmaxf(m, __shfl_xor_sync(FULL, m, 2));
            m = fmaxf(m, __shfl_xor_sync(FULL, m, 1));
            float ex = __expf(v.x - m);
            float ey = __expf(v.y - m);
            float ez = __expf(v.z - m);
            float ew = __expf(v.w - m);
            float s = (ex + ey) + (ez + ew);
            s += __shfl_xor_sync(FULL, s, 8);
            s += __shfl_xor_sync(FULL, s, 4);
            s += __shfl_xor_sync(FULL, s, 2);
            s += __shfl_xor_sync(FULL, s, 1);
            float rc = __frcp_rn(s);
            float4 o;
            o.x = ex * rc; o.y = ey * rc; o.z = ez * rc; o.w = ew * rc;
            float4* od = r ? o41 : o40;
            __stcs(&od[2 + 32 * j + lane], o);  // coalesced 512B store
        }
    }
}

extern "C" void kernel_launch(void* const* d_in, const int* in_sizes, int n_in,
                              void* d_out, int out_size)
{
    const float* x = (const float*)d_in[0];
    float* out = (float*)d_out;

    int nrows = in_sizes[0] / NCOLS;           // 65536
    int rows_per_warp = 2;
    int warps = (nrows + rows_per_warp - 1) / rows_per_warp;  // 32768
    int warps_per_block = 8;                   // 256 threads
    int blocks = (warps + warps_per_block - 1) / warps_per_block;  // 4096
    hsoftmax_kernel<<<blocks, warps_per_block * 32>>>(x, out, nrows);
}

// round 3
// speedup vs baseline: 1.0007x; 1.0007x over previous
#include <cuda_runtime.h>
#include <math_constants.h>

// HierarchicalSoftmax: x [B, 520] fp32. Per row: softmax over cols [0,8)
// (heads) and over each 64-col children group g: [8+64g, 8+64(g+1)).
// All boundaries are float4-aligned; a pair of adjacent children groups is
// 32 contiguous float4s (512B) -> one warp-wide LDG.128 is fully coalesced
// and each 16-lane half-warp owns exactly one segment (butterfly offsets
// 8,4,2,1 stay inside the half-warp).
//
// R3: back to ONE row per warp (R2's 2-row variant blew registers 34->52 and
// cut resident warps 56->32/SM, losing chip-wide MLP). Changes vs R1:
//   - 128-thread blocks: 15 resident CTAs x 4 warps = 60/64 warps theoretical
//     (vs 56/64 at 256 threads) and finer CTA interleaving at the L1tex queue.
//   - __ldcs on the read stream (touch-once; evict-first preserves L2 for the
//     lazily-draining write stream). Stores left default write-back.

#define NCOLS 520

__global__ __launch_bounds__(128) void hsoftmax_kernel(
    const float* __restrict__ x,
    float* __restrict__ out,
    int nrows)
{
    const unsigned FULL = 0xffffffffu;
    int warp = (blockIdx.x * blockDim.x + threadIdx.x) >> 5;
    int lane = threadIdx.x & 31;
    if (warp >= nrows) return;

    const float*  xrow = x   + (size_t)warp * NCOLS;
    float*        orow = out + (size_t)warp * NCOLS;
    const float4* x4   = reinterpret_cast<const float4*>(xrow);
    float4*       o4   = reinterpret_cast<float4*>(orow);

    // ---- Issue all loads up front (MLP=5 per warp) ----
    // Heads: lanes 0..7 load one scalar each (single 32B sector, row-aligned).
    float hv = (lane < 8) ? __ldcs(xrow + lane) : -CUDART_INF_F;

    // Children pairs j=0..3: warp-wide coalesced 512B LDG.128 each.
    float4 v0 = __ldcs(&x4[2 + 32 * 0 + lane]);
    float4 v1 = __ldcs(&x4[2 + 32 * 1 + lane]);
    float4 v2 = __ldcs(&x4[2 + 32 * 2 + lane]);
    float4 v3 = __ldcs(&x4[2 + 32 * 3 + lane]);

    // ---- Heads softmax (width-8 butterfly over lanes 0..7) ----
    {
        float m = hv;
        m = fmaxf(m, __shfl_xor_sync(FULL, m, 4));
        m = fmaxf(m, __shfl_xor_sync(FULL, m, 2));
        m = fmaxf(m, __shfl_xor_sync(FULL, m, 1));
        float e = __expf(hv - m);
        float s = e;
        s += __shfl_xor_sync(FULL, s, 4);
        s += __shfl_xor_sync(FULL, s, 2);
        s += __shfl_xor_sync(FULL, s, 1);
        if (lane < 8) orow[lane] = e / s;
    }

    // ---- Children: each 16-lane half owns one 64-elem group ----
    float4 vv[4] = {v0, v1, v2, v3};
#pragma unroll
    for (int j = 0; j < 4; ++j) {
        float4 v = vv[j];
        float m = fmaxf(fmaxf(v.x, v.y), fmaxf(v.z, v.w));
        m = fmaxf(m, __shfl_xor_sync(FULL, m, 8));
        m = fmaxf(m, __shfl_xor_sync(FULL, m, 4));
        m = fmaxf(m, __shfl_xor_sync(FULL, m, 2));
        m = fmaxf(m, __shfl_xor_sync(FULL, m, 1));
        float ex = __expf(v.x - m);
        float ey = __expf(v.y - m);
        float ez = __expf(v.z - m);
        float ew = __expf(v.w - m);
        float s = (ex + ey) + (ez + ew);
        s += __shfl_xor_sync(FULL, s, 8);
        s += __shfl_xor_sync(FULL, s, 4);
        s += __shfl_xor_sync(FULL, s, 2);
        s += __shfl_xor_sync(FULL, s, 1);
        float r = __frcp_rn(s);
        float4 o;
        o.x = ex * r; o.y = ey * r; o.z = ez * r; o.w = ew * r;
        o4[2 + 32 * j + lane] = o;   // coalesced 512B store
    }
}

extern "C" void kernel_launch(void* const* d_in, const int* in_sizes, int n_in,
                              void* d_out, int out_size)
{
    const float* x = (const float*)d_in[0];
    float* out = (float*)d_out;

    int nrows = in_sizes[0] / NCOLS;   // 65536
    int warps_per_block = 4;           // 128 threads
    int blocks = (nrows + warps_per_block - 1) / warps_per_block;  // 16384
    hsoftmax_kernel<<<blocks, warps_per_block * 32>>>(x, out, nrows);
}